// round 17
// baseline (speedup 1.0000x reference)
#include <cuda_runtime.h>
#include <cuda_fp16.h>
#include <math.h>

#define HID    896
#define INTERD 2560
#define NEXP   16
#define TOPK   4
#define NTOK   2048
#define NSLOT  (NTOK*TOPK)
#define KPA    24   // A-tile pitch (halves): rows 48B, uint4-aligned
#define KPB    20   // B-tile pitch (halves): filled via 2-byte split_store (R8 path)

// ---------------- mma.sync m16n8k16 f16 -> f32 ---------------------------------
__device__ __forceinline__ void mma16816(float c[4], const unsigned a[4], const unsigned b[2]) {
    asm volatile(
        "mma.sync.aligned.m16n8k16.row.col.f32.f16.f16.f32 "
        "{%0,%1,%2,%3}, {%4,%5,%6,%7}, {%8,%9}, {%0,%1,%2,%3};\n"
        : "+f"(c[0]), "+f"(c[1]), "+f"(c[2]), "+f"(c[3])
        : "r"(a[0]), "r"(a[1]), "r"(a[2]), "r"(a[3]), "r"(b[0]), "r"(b[1]));
}

__device__ __forceinline__ void split_store(float x, __half* ph, __half* pl) {
    __half h = __float2half_rn(x);
    *ph = h;
    *pl = __float2half_rn(x - __half2float(h));
}

__device__ __forceinline__ float silu_mul(float g, float u) {
    return g / (1.f + __expf(-g)) * u;
}

// ---------------- static device scratch (~149 MB total) -------------------------
__device__ float g_probsum[NEXP];
__device__ int   g_count[NEXP];
__device__ int   g_cursor[NEXP];
__device__ int   g_offset[NEXP];
__device__ int   g_topk_idx[NTOK][TOPK];
__device__ float g_topk_w[NTOK][TOPK];
__device__ int   g_slot_token[NSLOT];
__device__ int   g_token_slot[NTOK][TOPK];

// split-fp16 activations (A-side only; weights remain fp32 inputs)
__device__ __half g_xh[(size_t)NTOK * HID];
__device__ __half g_xl[(size_t)NTOK * HID];
// intermediate h, split: slots [0,NSLOT) routed, [NSLOT, NSLOT+NTOK) shared
__device__ __half g_h_h[(size_t)(NSLOT + NTOK) * INTERD];
__device__ __half g_h_l[(size_t)(NSLOT + NTOK) * INTERD];

__device__ float g_oshared[(size_t)NTOK * HID];
__device__ float g_drouted[(size_t)NSLOT * HID];

// ---------------- init ----------------------------------------------------------
__global__ void init_kernel() {
    int i = threadIdx.x;
    if (i < NEXP) { g_probsum[i] = 0.f; g_count[i] = 0; g_cursor[i] = 0; }
}

// ---------------- router --------------------------------------------------------
__global__ void router_kernel(const float* __restrict__ x,
                              const float* __restrict__ rw) {
    int t = blockIdx.x, lane = threadIdx.x;
    const float* xr = x + (size_t)t * HID;
    __shared__ float logits[NEXP];
    for (int e = 0; e < NEXP; e++) {
        float s = 0.f;
        for (int k = lane; k < HID; k += 32) s += xr[k] * rw[k * NEXP + e];
        #pragma unroll
        for (int o = 16; o > 0; o >>= 1) s += __shfl_down_sync(0xffffffffu, s, o);
        if (lane == 0) logits[e] = s;
    }
    __syncwarp();
    if (lane != 0) return;
    float mx = -1e30f;
    #pragma unroll
    for (int e = 0; e < NEXP; e++) mx = fmaxf(mx, logits[e]);
    float p[NEXP]; float psum = 0.f;
    #pragma unroll
    for (int e = 0; e < NEXP; e++) { p[e] = __expf(logits[e] - mx); psum += p[e]; }
    float inv = 1.f / psum;
    #pragma unroll
    for (int e = 0; e < NEXP; e++) p[e] *= inv;
    bool used[NEXP] = {};
    int idx[TOPK]; float val[TOPK]; float wsum = 0.f;
    #pragma unroll
    for (int k = 0; k < TOPK; k++) {
        int best = -1; float bv = -1.f;
        #pragma unroll
        for (int e = 0; e < NEXP; e++)
            if (!used[e] && p[e] > bv) { bv = p[e]; best = e; }
        used[best] = true; idx[k] = best; val[k] = bv; wsum += bv;
    }
    float winv = 1.f / (wsum + 1e-8f);
    #pragma unroll
    for (int k = 0; k < TOPK; k++) {
        g_topk_idx[t][k] = idx[k];
        g_topk_w[t][k]   = val[k] * winv;
        atomicAdd(&g_count[idx[k]], 1);
    }
    #pragma unroll
    for (int e = 0; e < NEXP; e++) atomicAdd(&g_probsum[e], p[e]);
}

// ---------------- scan + loss ---------------------------------------------------
__global__ void scan_loss_kernel(float* __restrict__ loss_out) {
    int off = 0; float loss = 0.f;
    for (int e = 0; e < NEXP; e++) {
        g_offset[e] = off; off += g_count[e];
        float f = (float)g_count[e] / (float)NTOK;
        float P = g_probsum[e] / (float)NTOK;
        loss += f * P;
    }
    *loss_out = (float)NEXP * loss;
}

// ---------------- slot assignment ----------------------------------------------
__global__ void assign_kernel() {
    int t = blockIdx.x * blockDim.x + threadIdx.x;
    if (t >= NTOK) return;
    #pragma unroll
    for (int k = 0; k < TOPK; k++) {
        int e = g_topk_idx[t][k];
        int pos = atomicAdd(&g_cursor[e], 1);
        int slot = g_offset[e] + pos;
        g_slot_token[slot] = t;
        g_token_slot[t][k] = slot;
    }
}

// ---------------- split x -------------------------------------------------------
__global__ void convert_x(const float* __restrict__ x) {
    int i = blockIdx.x * blockDim.x + threadIdx.x;
    if (i >= NTOK * HID) return;
    float v = x[i];
    __half h = __float2half_rn(v);
    g_xh[i] = h;
    g_xl[i] = __float2half_rn(v - __half2float(h));
}

// ---------------- gate/up GEMM: A pre-split, B split in-kernel (R8 path) --------
// 128x64 tile, 8 warps (4m x 2n), warp tile 32x32. grid.z: 0..15 routed, 16 shared.
// smem = 24576 (A, pitch 24) + 20480 (B, pitch 20) = 45056 B
__global__ void __launch_bounds__(256) gateup_gemm(
    const float* __restrict__ WgBase,
    const float* __restrict__ WuBase,
    const float* __restrict__ Sg,
    const float* __restrict__ Su)
{
    const int K = HID, N = INTERD;
    int e = blockIdx.z;
    int M; const int* rowmap; const float* Bg; const float* Bu;
    __half *outh, *outl;
    if (e < NEXP) {
        M = g_count[e];
        rowmap = g_slot_token + g_offset[e];
        Bg = WgBase + (size_t)e * K * N;
        Bu = WuBase + (size_t)e * K * N;
        size_t ho = (size_t)g_offset[e] * INTERD;
        outh = g_h_h + ho; outl = g_h_l + ho;
    } else {
        M = NTOK; rowmap = nullptr; Bg = Sg; Bu = Su;
        outh = g_h_h + (size_t)NSLOT * INTERD;
        outl = g_h_l + (size_t)NSLOT * INTERD;
    }
    int m0 = blockIdx.y * 128;
    if (m0 >= M) return;
    int n0 = blockIdx.x * 64;

    __shared__ __half Ah[2][128][KPA], Al[2][128][KPA];
    __shared__ __half Bgh[2][64][KPB], Bgl[2][64][KPB];
    __shared__ __half Buh[2][64][KPB], Bul[2][64][KPB];

    int tid  = threadIdx.x;
    // A fill (pre-split copies): (row, hi/lo)
    int arow = tid >> 1;          // 0..127
    int asel = tid & 1;
    // B fill (R8 in-kernel split): k-row 0..15, n-cols bcol..bcol+3
    int brow = tid >> 4;          // 0..15
    int bcol = (tid & 15) * 4;    // 0..60
    int warp = tid >> 5;
    int wm   = warp & 3, wn = warp >> 2;
    int lane = tid & 31;
    int g    = lane >> 2, tig = lane & 3;

    float accg[2][4][4] = {}, accu[2][4][4] = {};

    int gm = m0 + arow;
    bool av = gm < M;
    const __half* asrc = nullptr;
    if (av) {
        int r = rowmap ? rowmap[gm] : gm;
        asrc = (asel ? g_xl : g_xh) + (size_t)r * HID;
    }
    const uint4 Z = make_uint4(0, 0, 0, 0);

    // preload tile 0
    {
        uint4 a0 = av ? *(const uint4*)(asrc) : Z;
        uint4 a1 = av ? *(const uint4*)(asrc + 8) : Z;
        __half* ad = asel ? &Al[0][arow][0] : &Ah[0][arow][0];
        *(uint4*)ad = a0; *(uint4*)(ad + 8) = a1;
        float4 bg = *(const float4*)(Bg + (size_t)brow * N + n0 + bcol);
        float4 bu = *(const float4*)(Bu + (size_t)brow * N + n0 + bcol);
        split_store(bg.x, &Bgh[0][bcol+0][brow], &Bgl[0][bcol+0][brow]);
        split_store(bg.y, &Bgh[0][bcol+1][brow], &Bgl[0][bcol+1][brow]);
        split_store(bg.z, &Bgh[0][bcol+2][brow], &Bgl[0][bcol+2][brow]);
        split_store(bg.w, &Bgh[0][bcol+3][brow], &Bgl[0][bcol+3][brow]);
        split_store(bu.x, &Buh[0][bcol+0][brow], &Bul[0][bcol+0][brow]);
        split_store(bu.y, &Buh[0][bcol+1][brow], &Bul[0][bcol+1][brow]);
        split_store(bu.z, &Buh[0][bcol+2][brow], &Bul[0][bcol+2][brow]);
        split_store(bu.w, &Buh[0][bcol+3][brow], &Bul[0][bcol+3][brow]);
    }
    __syncthreads();

    int cur = 0;
    for (int kt = 0; kt < K; kt += 16) {
        bool has_next = (kt + 16) < K;
        uint4 an0 = Z, an1 = Z;
        float4 bgn, bun;
        if (has_next) {
            if (av) { an0 = *(const uint4*)(asrc + kt + 16); an1 = *(const uint4*)(asrc + kt + 24); }
            bgn = *(const float4*)(Bg + (size_t)(kt + 16 + brow) * N + n0 + bcol);
            bun = *(const float4*)(Bu + (size_t)(kt + 16 + brow) * N + n0 + bcol);
        }
        unsigned ahf[2][4], alf[2][4];
        #pragma unroll
        for (int ma = 0; ma < 2; ma++) {
            int r = wm * 32 + ma * 16 + g;
            ahf[ma][0] = *(const unsigned*)&Ah[cur][r    ][2*tig    ];
            ahf[ma][1] = *(const unsigned*)&Ah[cur][r + 8][2*tig    ];
            ahf[ma][2] = *(const unsigned*)&Ah[cur][r    ][2*tig + 8];
            ahf[ma][3] = *(const unsigned*)&Ah[cur][r + 8][2*tig + 8];
            alf[ma][0] = *(const unsigned*)&Al[cur][r    ][2*tig    ];
            alf[ma][1] = *(const unsigned*)&Al[cur][r + 8][2*tig    ];
            alf[ma][2] = *(const unsigned*)&Al[cur][r    ][2*tig + 8];
            alf[ma][3] = *(const unsigned*)&Al[cur][r + 8][2*tig + 8];
        }
        #pragma unroll
        for (int na = 0; na < 4; na++) {
            int n = wn * 32 + na * 8 + g;
            unsigned bh[2], bl[2], uh[2], ul[2];
            bh[0] = *(const unsigned*)&Bgh[cur][n][2*tig    ];
            bh[1] = *(const unsigned*)&Bgh[cur][n][2*tig + 8];
            bl[0] = *(const unsigned*)&Bgl[cur][n][2*tig    ];
            bl[1] = *(const unsigned*)&Bgl[cur][n][2*tig + 8];
            uh[0] = *(const unsigned*)&Buh[cur][n][2*tig    ];
            uh[1] = *(const unsigned*)&Buh[cur][n][2*tig + 8];
            ul[0] = *(const unsigned*)&Bul[cur][n][2*tig    ];
            ul[1] = *(const unsigned*)&Bul[cur][n][2*tig + 8];
            #pragma unroll
            for (int ma = 0; ma < 2; ma++) {
                mma16816(accg[ma][na], ahf[ma], bh);
                mma16816(accg[ma][na], alf[ma], bh);
                mma16816(accg[ma][na], ahf[ma], bl);
                mma16816(accu[ma][na], ahf[ma], uh);
                mma16816(accu[ma][na], alf[ma], uh);
                mma16816(accu[ma][na], ahf[ma], ul);
            }
        }
        if (has_next) {
            int nb = cur ^ 1;
            __half* ad = asel ? &Al[nb][arow][0] : &Ah[nb][arow][0];
            *(uint4*)ad = an0; *(uint4*)(ad + 8) = an1;
            split_store(bgn.x, &Bgh[nb][bcol+0][brow], &Bgl[nb][bcol+0][brow]);
            split_store(bgn.y, &Bgh[nb][bcol+1][brow], &Bgl[nb][bcol+1][brow]);
            split_store(bgn.z, &Bgh[nb][bcol+2][brow], &Bgl[nb][bcol+2][brow]);
            split_store(bgn.w, &Bgh[nb][bcol+3][brow], &Bgl[nb][bcol+3][brow]);
            split_store(bun.x, &Buh[nb][bcol+0][brow], &Bul[nb][bcol+0][brow]);
            split_store(bun.y, &Buh[nb][bcol+1][brow], &Bul[nb][bcol+1][brow]);
            split_store(bun.z, &Buh[nb][bcol+2][brow], &Bul[nb][bcol+2][brow]);
            split_store(bun.w, &Buh[nb][bcol+3][brow], &Bul[nb][bcol+3][brow]);
            __syncthreads();
            cur = nb;
        }
    }
    // epilogue: silu(g)*u, written as split halves for down's A-feed
    #pragma unroll
    for (int ma = 0; ma < 2; ma++) {
        int r0 = m0 + wm * 32 + ma * 16 + g;
        int r1 = r0 + 8;
        #pragma unroll
        for (int na = 0; na < 4; na++) {
            int c = n0 + wn * 32 + na * 8 + 2 * tig;
            if (r0 < M) {
                float h0 = silu_mul(accg[ma][na][0], accu[ma][na][0]);
                float h1 = silu_mul(accg[ma][na][1], accu[ma][na][1]);
                __half h0h = __float2half_rn(h0), h1h = __float2half_rn(h1);
                __half h0l = __float2half_rn(h0 - __half2float(h0h));
                __half h1l = __float2half_rn(h1 - __half2float(h1h));
                *(__half2*)(outh + (size_t)r0 * N + c) = __halves2half2(h0h, h1h);
                *(__half2*)(outl + (size_t)r0 * N + c) = __halves2half2(h0l, h1l);
            }
            if (r1 < M) {
                float h0 = silu_mul(accg[ma][na][2], accu[ma][na][2]);
                float h1 = silu_mul(accg[ma][na][3], accu[ma][na][3]);
                __half h0h = __float2half_rn(h0), h1h = __float2half_rn(h1);
                __half h0l = __float2half_rn(h0 - __half2float(h0h));
                __half h1l = __float2half_rn(h1 - __half2float(h1h));
                *(__half2*)(outh + (size_t)r1 * N + c) = __halves2half2(h0h, h1h);
                *(__half2*)(outl + (size_t)r1 * N + c) = __halves2half2(h0l, h1l);
            }
        }
    }
}

// ---------------- down GEMM: A pre-split (h), B split in-kernel (R8 path) -------
// smem = 24576 (A) + 10240 (B) = 34816 B
__global__ void __launch_bounds__(256) down_gemm(
    const float* __restrict__ WdBase,
    const float* __restrict__ Sd)
{
    const int K = INTERD, N = HID;
    int e = blockIdx.z;
    int M; size_t abase; const float* B; float* out;
    if (e < NEXP) {
        M = g_count[e];
        abase = (size_t)g_offset[e] * INTERD;
        B = WdBase + (size_t)e * K * N;
        out = g_drouted + (size_t)g_offset[e] * N;
    } else {
        M = NTOK;
        abase = (size_t)NSLOT * INTERD;
        B = Sd;
        out = g_oshared;
    }
    int m0 = blockIdx.y * 128;
    if (m0 >= M) return;
    int n0 = blockIdx.x * 64;

    __shared__ __half Ah[2][128][KPA], Al[2][128][KPA];
    __shared__ __half Bh[2][64][KPB],  Bl[2][64][KPB];

    int tid  = threadIdx.x;
    int arow = tid >> 1, asel = tid & 1;
    int brow = tid >> 4;          // 0..15
    int bcol = (tid & 15) * 4;    // 0..60
    int warp = tid >> 5;
    int wm   = warp & 3, wn = warp >> 2;
    int lane = tid & 31;
    int g    = lane >> 2, tig = lane & 3;

    float acc[2][4][4] = {};
    int gm = m0 + arow;
    bool av = gm < M;
    const __half* asrc = nullptr;
    if (av) asrc = (asel ? g_h_l : g_h_h) + abase + (size_t)gm * INTERD;
    const uint4 Z = make_uint4(0, 0, 0, 0);

    {
        uint4 a0 = av ? *(const uint4*)(asrc) : Z;
        uint4 a1 = av ? *(const uint4*)(asrc + 8) : Z;
        __half* ad = asel ? &Al[0][arow][0] : &Ah[0][arow][0];
        *(uint4*)ad = a0; *(uint4*)(ad + 8) = a1;
        float4 bv = *(const float4*)(B + (size_t)brow * N + n0 + bcol);
        split_store(bv.x, &Bh[0][bcol+0][brow], &Bl[0][bcol+0][brow]);
        split_store(bv.y, &Bh[0][bcol+1][brow], &Bl[0][bcol+1][brow]);
        split_store(bv.z, &Bh[0][bcol+2][brow], &Bl[0][bcol+2][brow]);
        split_store(bv.w, &Bh[0][bcol+3][brow], &Bl[0][bcol+3][brow]);
    }
    __syncthreads();

    int cur = 0;
    for (int kt = 0; kt < K; kt += 16) {
        bool has_next = (kt + 16) < K;
        uint4 an0 = Z, an1 = Z;
        float4 bn;
        if (has_next) {
            if (av) { an0 = *(const uint4*)(asrc + kt + 16); an1 = *(const uint4*)(asrc + kt + 24); }
            bn = *(const float4*)(B + (size_t)(kt + 16 + brow) * N + n0 + bcol);
        }
        unsigned ahf[2][4], alf[2][4];
        #pragma unroll
        for (int ma = 0; ma < 2; ma++) {
            int r = wm * 32 + ma * 16 + g;
            ahf[ma][0] = *(const unsigned*)&Ah[cur][r    ][2*tig    ];
            ahf[ma][1] = *(const unsigned*)&Ah[cur][r + 8][2*tig    ];
            ahf[ma][2] = *(const unsigned*)&Ah[cur][r    ][2*tig + 8];
            ahf[ma][3] = *(const unsigned*)&Ah[cur][r + 8][2*tig + 8];
            alf[ma][0] = *(const unsigned*)&Al[cur][r    ][2*tig    ];
            alf[ma][1] = *(const unsigned*)&Al[cur][r + 8][2*tig    ];
            alf[ma][2] = *(const unsigned*)&Al[cur][r    ][2*tig + 8];
            alf[ma][3] = *(const unsigned*)&Al[cur][r + 8][2*tig + 8];
        }
        #pragma unroll
        for (int na = 0; na < 4; na++) {
            int n = wn * 32 + na * 8 + g;
            unsigned bh[2], bl[2];
            bh[0] = *(const unsigned*)&Bh[cur][n][2*tig    ];
            bh[1] = *(const unsigned*)&Bh[cur][n][2*tig + 8];
            bl[0] = *(const unsigned*)&Bl[cur][n][2*tig    ];
            bl[1] = *(const unsigned*)&Bl[cur][n][2*tig + 8];
            #pragma unroll
            for (int ma = 0; ma < 2; ma++) {
                mma16816(acc[ma][na], ahf[ma], bh);
                mma16816(acc[ma][na], alf[ma], bh);
                mma16816(acc[ma][na], ahf[ma], bl);
            }
        }
        if (has_next) {
            int nb = cur ^ 1;
            __half* ad = asel ? &Al[nb][arow][0] : &Ah[nb][arow][0];
            *(uint4*)ad = an0; *(uint4*)(ad + 8) = an1;
            split_store(bn.x, &Bh[nb][bcol+0][brow], &Bl[nb][bcol+0][brow]);
            split_store(bn.y, &Bh[nb][bcol+1][brow], &Bl[nb][bcol+1][brow]);
            split_store(bn.z, &Bh[nb][bcol+2][brow], &Bl[nb][bcol+2][brow]);
            split_store(bn.w, &Bh[nb][bcol+3][brow], &Bl[nb][bcol+3][brow]);
            __syncthreads();
            cur = nb;
        }
    }
    #pragma unroll
    for (int ma = 0; ma < 2; ma++) {
        int r0 = m0 + wm * 32 + ma * 16 + g;
        int r1 = r0 + 8;
        #pragma unroll
        for (int na = 0; na < 4; na++) {
            int c = n0 + wn * 32 + na * 8 + 2 * tig;
            if (r0 < M) {
                float* o = out + (size_t)r0 * N + c;
                o[0] = acc[ma][na][0];
                o[1] = acc[ma][na][1];
            }
            if (r1 < M) {
                float* o = out + (size_t)r1 * N + c;
                o[0] = acc[ma][na][2];
                o[1] = acc[ma][na][3];
            }
        }
    }
}

// ---------------- final combine (deterministic) ---------------------------------
__global__ void combine_kernel(float* __restrict__ outp) {
    const int NV = HID / 4;
    int i = blockIdx.x * blockDim.x + threadIdx.x;
    if (i >= NTOK * NV) return;
    int t = i / NV, dv = i - t * NV;
    const float4* sh4 = (const float4*)g_oshared;
    float4 v = sh4[i];
    #pragma unroll
    for (int k = 0; k < TOPK; k++) {
        int slot = g_token_slot[t][k];
        float w = g_topk_w[t][k];
        float4 r = *(const float4*)(g_drouted + (size_t)slot * HID + dv * 4);
        v.x = fmaf(w, r.x, v.x); v.y = fmaf(w, r.y, v.y);
        v.z = fmaf(w, r.z, v.z); v.w = fmaf(w, r.w, v.w);
    }
    ((float4*)outp)[i] = v;
}

// ---------------- launch ---------------------------------------------------------
extern "C" void kernel_launch(void* const* d_in, const int* in_sizes, int n_in,
                              void* d_out, int out_size) {
    const float* x  = (const float*)d_in[0];
    const float* rw = (const float*)d_in[1];
    const float* Wg = (const float*)d_in[2];
    const float* Wu = (const float*)d_in[3];
    const float* Wd = (const float*)d_in[4];
    const float* Sg = (const float*)d_in[5];
    const float* Su = (const float*)d_in[6];
    const float* Sd = (const float*)d_in[7];
    float* out = (float*)d_out;

    init_kernel<<<1, 32>>>();
    router_kernel<<<NTOK, 32>>>(x, rw);
    scan_loss_kernel<<<1, 1>>>(out + (out_size - 1));
    assign_kernel<<<NTOK / 256, 256>>>();

    convert_x<<<(NTOK * HID + 255) / 256, 256>>>(x);

    // z: 0..15 routed experts, 16 = shared expert
    gateup_gemm<<<dim3(INTERD / 64, NTOK / 128, NEXP + 1), 256>>>(Wg, Wu, Sg, Su);
    down_gemm<<<dim3(HID / 64, NTOK / 128, NEXP + 1), 256>>>(Wd, Sd);

    combine_kernel<<<(NTOK * (HID / 4) + 255) / 256, 256>>>(out);
}